// round 15
// baseline (speedup 1.0000x reference)
#include <cuda_runtime.h>
#include <cstdint>

// Shapes (fixed by the benchmark)
#define B 4
#define L 2048
#define H 8
#define D 64
#define SK 40          // sample_k
#define U 40           // top-k queries kept
#define BH (B*H)       // 32
#define C (H*D)        // 512 columns for cumsum view

// Attention chunking
#define KCH 128        // keys per chunk in dense attention
#define NCHK (L/KCH)   // 16
#define PKS 68         // Ks pitch (floats): conflict-free float4 key-major reads
#define PVS 66         // Vs pitch (floats): conflict-free float2 d-major reads

// Cumsum chunking
#define NCH 128
#define CHUNK (L/NCH)  // 16

// -------- scratch (device globals; no allocation allowed) --------
__device__ float g_M[BH * L];
__device__ int   g_Mtop[BH * U];
__device__ float g_pm[BH * U * NCHK];
__device__ float g_pl[BH * U * NCHK];
__device__ float g_pacc[BH * U * NCHK * D];
__device__ float g_csum[B * NCH * C];

// ===================== Stage 1: sampled scores -> M =====================
// Block per query q. Thread t = (b=t>>6, h=(t>>3)&7, g=t&7); thread owns dims
// [8g, 8g+8). Samples in batches of 8: 16 independent LDG.128, 8 partial dots,
// 3-stage butterfly reduce-scatter (7 shuffles / 8 samples).
__global__ void __launch_bounds__(256) k_sample_scores(
    const float* __restrict__ Q,
    const float* __restrict__ K,
    const int*   __restrict__ idx)
{
    __shared__ int sidx[SK];
    int q = blockIdx.x;
    int t = threadIdx.x;
    int b = t >> 6;
    int h = (t >> 3) & 7;
    int g = t & 7;

    if (t < SK) sidx[t] = idx[q * SK + t];
    __syncthreads();

    const float* qp = Q + (((size_t)b * L + q) * H + h) * D + g * 8;
    float4 qa = *(const float4*)qp;
    float4 qb = *(const float4*)(qp + 4);

    const size_t hoff = (size_t)h * D + (size_t)g * 8;
    const float* Kb = K + (size_t)b * L * (H * D) + hoff;

    const int b0 = g & 1, b1 = (g >> 1) & 1, b2 = (g >> 2) & 1;

    float mx = -1e30f, sm = 0.f;

    for (int bi = 0; bi < 5; bi++) {
        float4 ka[8], kc[8];
        #pragma unroll
        for (int k = 0; k < 8; k++) {
            const float* kp = Kb + (size_t)sidx[bi * 8 + k] * (H * D);
            ka[k] = *(const float4*)kp;
            kc[k] = *(const float4*)(kp + 4);
        }
        float p[8];
        #pragma unroll
        for (int k = 0; k < 8; k++)
            p[k] = qa.x * ka[k].x + qa.y * ka[k].y + qa.z * ka[k].z + qa.w * ka[k].w
                 + qb.x * kc[k].x + qb.y * kc[k].y + qb.z * kc[k].z + qb.w * kc[k].w;

        float q4[4];
        #pragma unroll
        for (int j = 0; j < 4; j++) {
            float keep = b0 ? p[2 * j + 1] : p[2 * j];
            float send = b0 ? p[2 * j]     : p[2 * j + 1];
            q4[j] = keep + __shfl_xor_sync(0xffffffffu, send, 1);
        }
        float r2[2];
        #pragma unroll
        for (int j = 0; j < 2; j++) {
            float keep = b1 ? q4[2 * j + 1] : q4[2 * j];
            float send = b1 ? q4[2 * j]     : q4[2 * j + 1];
            r2[j] = keep + __shfl_xor_sync(0xffffffffu, send, 2);
        }
        float keep = b2 ? r2[1] : r2[0];
        float send = b2 ? r2[0] : r2[1];
        float d = keep + __shfl_xor_sync(0xffffffffu, send, 4);

        mx = fmaxf(mx, d);
        sm += d;
    }

    #pragma unroll
    for (int o = 1; o < 8; o <<= 1) {
        mx = fmaxf(mx, __shfl_xor_sync(0xffffffffu, mx, o));
        sm += __shfl_xor_sync(0xffffffffu, sm, o);
    }
    if (g == 0)
        g_M[(t >> 3) * L + q] = mx - sm * (1.0f / SK);
}

// ===================== Stage 2: exact top-U: 2 radix passes + rank =========
__device__ __forceinline__ unsigned f2ord(float f)
{
    unsigned u = __float_as_uint(f);
    return (u & 0x80000000u) ? ~u : (u | 0x80000000u);
}

#define CAND 1024

__global__ void __launch_bounds__(1024) k_topk()
{
    __shared__ unsigned keys[L];
    __shared__ int hist[256];
    __shared__ unsigned s_prefix;
    __shared__ int s_rem, s_cnt, s_ecnt;
    __shared__ int cand[CAND];
    __shared__ int tmpi[U];

    int bh = blockIdx.x;
    int t = threadIdx.x;

    unsigned k0 = f2ord(g_M[bh * L + t]);
    unsigned k1 = f2ord(g_M[bh * L + t + 1024]);
    keys[t] = k0;
    keys[t + 1024] = k1;
    if (t == 0) { s_prefix = 0u; s_rem = U; s_cnt = 0; s_ecnt = 0; }
    __syncthreads();

    unsigned mask = 0u;
    #pragma unroll
    for (int shift = 24; shift >= 16; shift -= 8) {
        if (t < 256) hist[t] = 0;
        __syncthreads();
        unsigned pre = s_prefix;
        if ((k0 & mask) == pre) atomicAdd(&hist[(k0 >> shift) & 255], 1);
        if ((k1 & mask) == pre) atomicAdd(&hist[(k1 >> shift) & 255], 1);
        __syncthreads();
        if (t < 32) {
            int rem = s_rem;
            int loc[8], sum = 0;
            #pragma unroll
            for (int j = 0; j < 8; j++) {
                loc[j] = hist[255 - (t * 8 + j)];
                sum += loc[j];
            }
            int pref = sum;
            #pragma unroll
            for (int o = 1; o < 32; o <<= 1) {
                int v = __shfl_up_sync(0xffffffffu, pref, o);
                if (t >= o) pref += v;
            }
            int c = pref - sum;
            #pragma unroll
            for (int j = 0; j < 8; j++) {
                int nc = c + loc[j];
                if (c < rem && nc >= rem) {        // exactly one (lane,j)
                    s_prefix = pre | ((unsigned)(255 - (t * 8 + j)) << shift);
                    s_rem = rem - c;
                }
                c = nc;
            }
        }
        mask |= (0xFFu << shift);
        __syncthreads();
    }

    unsigned pre16 = s_prefix;
    int rem = s_rem;
    {
        unsigned hi = k0 & 0xFFFF0000u;
        if (hi > pre16) tmpi[atomicAdd(&s_cnt, 1)] = t;
        else if (hi == pre16) {
            int p = atomicAdd(&s_ecnt, 1);
            if (p < CAND) cand[p] = t;
        }
        hi = k1 & 0xFFFF0000u;
        if (hi > pre16) tmpi[atomicAdd(&s_cnt, 1)] = t + 1024;
        else if (hi == pre16) {
            int p = atomicAdd(&s_ecnt, 1);
            if (p < CAND) cand[p] = t + 1024;
        }
    }
    __syncthreads();

    int ncand = min(s_ecnt, CAND);
    int base = s_cnt;                        // == U - rem by construction
    if (t < ncand) {
        int i = cand[t];
        unsigned k = keys[i];
        int rank = 0;
        for (int j = 0; j < ncand; j++) {
            int cj = cand[j];
            unsigned kj = keys[cj];
            rank += (kj > k) || (kj == k && cj < i);
        }
        if (rank < rem) tmpi[base + rank] = i;
    }
    __syncthreads();

    // rank-sort ascending (indices distinct); g_Mtop consumed as a set
    if (t < U) {
        int v = tmpi[t], r = 0;
        #pragma unroll
        for (int j = 0; j < U; j++) r += (tmpi[j] < v);
        g_Mtop[bh * U + r] = v;
    }
}

// ===================== Stage 3: cumsum of V along L -> out =====================
__global__ void k_cumsum_a(const float* __restrict__ V)
{
    int blk = blockIdx.x;
    int b = blk / NCH, ch = blk % NCH;
    int c = threadIdx.x;
    const float* base = V + ((size_t)b * L + ch * CHUNK) * C + c;
    float s = 0.f;
    #pragma unroll
    for (int l = 0; l < CHUNK; l++) s += base[(size_t)l * C];
    g_csum[((size_t)b * NCH + ch) * C + c] = s;
}

__global__ void k_cumsum_c(const float* __restrict__ V, float* __restrict__ out)
{
    int blk = blockIdx.x;
    int b = blk / NCH, ch = blk % NCH;
    int c = threadIdx.x;
    float run = 0.f;
    for (int j = 0; j < ch; j++)
        run += g_csum[((size_t)b * NCH + j) * C + c];
    const float* vb = V   + ((size_t)b * L + ch * CHUNK) * C + c;
    float*       ob = out + ((size_t)b * L + ch * CHUNK) * C + c;
    #pragma unroll
    for (int l0 = 0; l0 < CHUNK; l0 += 8) {
        float v[8];
        #pragma unroll
        for (int j = 0; j < 8; j++) v[j] = vb[(size_t)(l0 + j) * C];
        #pragma unroll
        for (int j = 0; j < 8; j++) {
            run += v[j];
            ob[(size_t)(l0 + j) * C] = run;
        }
    }
}

// ===================== Stage 4: dense attention partials =====================
// Skipped (warp,chunk) pairs write NOTHING: the reduce kernel loops only over
// chunks with k0 <= p (their contribution is provably (m=-1e30,l=0,acc=0)).
__global__ void __launch_bounds__(256) k_attn_partial(
    const float* __restrict__ Q,
    const float* __restrict__ K,
    const float* __restrict__ V)
{
    extern __shared__ float smf[];
    float* Ks = smf;                       // KCH * PKS
    float* Vs = Ks + KCH * PKS;            // KCH * PVS
    float* Qs = Vs + KCH * PVS;            // U * D
    float* pb = Qs + U * D;                // 8 warps * 5 q * 128 k
    int*   ps = (int*)(pb + 8 * 5 * KCH);  // U

    int bh = blockIdx.x >> 4;
    int ch = blockIdx.x & 15;
    int b = bh >> 3, h = bh & 7;
    int t = threadIdx.x;
    int k0 = ch * KCH;

    for (int i = t; i < KCH * D; i += 256) {
        int r = i >> 6, d = i & 63;
        size_t gidx = (((size_t)b * L + (k0 + r)) * H + h) * D + d;
        Ks[r * PKS + d] = K[gidx];
        Vs[r * PVS + d] = V[gidx];
    }
    if (t < U) ps[t] = g_Mtop[bh * U + t];
    __syncthreads();
    for (int i = t; i < U * D; i += 256) {
        int u = i >> 6, d = i & 63;
        Qs[i] = Q[(((size_t)b * L + ps[u]) * H + h) * D + d];
    }
    __syncthreads();

    int w = t >> 5, lane = t & 31;
    const float4* Qb = (const float4*)Qs;

    // whole-warp causal skip (ps sorted ascending; no block barriers below).
    // Reduce never reads these (chunk,query) slots -> no writes needed.
    if (ps[w * 5 + 4] < k0) return;

    float s4[5][4];
    #pragma unroll
    for (int q = 0; q < 5; q++)
        #pragma unroll
        for (int g = 0; g < 4; g++) s4[q][g] = 0.f;

    #pragma unroll 4
    for (int i = 0; i < 16; i++) {
        float4 kk[4];
        #pragma unroll
        for (int g = 0; g < 4; g++)
            kk[g] = *(const float4*)&Ks[(g * 32 + lane) * PKS + 4 * i];
        #pragma unroll
        for (int q = 0; q < 5; q++) {
            float4 qv = Qb[(w * 5 + q) * 16 + i];
            #pragma unroll
            for (int g = 0; g < 4; g++)
                s4[q][g] += qv.x * kk[g].x + qv.y * kk[g].y
                          + qv.z * kk[g].z + qv.w * kk[g].w;
        }
    }

    #pragma unroll
    for (int q = 0; q < 5; q++) {
        int u = w * 5 + q;
        int p = ps[u];
        float sc[4]; bool ok[4];
        float m = -1e30f;
        #pragma unroll
        for (int g = 0; g < 4; g++) {
            sc[g] = s4[q][g] * 0.125f;             // 1/sqrt(64)
            ok[g] = (k0 + g * 32 + lane) <= p;
            m = fmaxf(m, ok[g] ? sc[g] : -1e30f);
        }
        #pragma unroll
        for (int o = 16; o; o >>= 1)
            m = fmaxf(m, __shfl_xor_sync(0xffffffffu, m, o));
        float l = 0.f;
        #pragma unroll
        for (int g = 0; g < 4; g++) {
            float pv = ok[g] ? __expf(sc[g] - m) : 0.f;
            l += pv;
            pb[w * (5 * KCH) + q * KCH + g * 32 + lane] = pv;
        }
        #pragma unroll
        for (int o = 16; o; o >>= 1)
            l += __shfl_xor_sync(0xffffffffu, l, o);
        if (lane == 0) {
            int pi = (bh * U + u) * NCHK + ch;
            g_pm[pi] = m;
            g_pl[pi] = l;
        }
    }
    __syncwarp();

    float2 acc[5];
    #pragma unroll
    for (int q = 0; q < 5; q++) acc[q] = make_float2(0.f, 0.f);

    #pragma unroll 4
    for (int k = 0; k < KCH; k += 4) {
        float2 v0 = *(const float2*)&Vs[(k + 0) * PVS + 2 * lane];
        float2 v1 = *(const float2*)&Vs[(k + 1) * PVS + 2 * lane];
        float2 v2 = *(const float2*)&Vs[(k + 2) * PVS + 2 * lane];
        float2 v3 = *(const float2*)&Vs[(k + 3) * PVS + 2 * lane];
        #pragma unroll
        for (int q = 0; q < 5; q++) {
            float4 pq = *(const float4*)&pb[w * (5 * KCH) + q * KCH + k];
            acc[q].x += pq.x * v0.x + pq.y * v1.x + pq.z * v2.x + pq.w * v3.x;
            acc[q].y += pq.x * v0.y + pq.y * v1.y + pq.z * v2.y + pq.w * v3.y;
        }
    }

    #pragma unroll
    for (int q = 0; q < 5; q++) {
        int u = w * 5 + q;
        int pi = (bh * U + u) * NCHK + ch;
        *(float2*)&g_pacc[(size_t)pi * D + 2 * lane] = acc[q];
    }
}

// ===================== Stage 5: combine partials, scatter rows =====================
// Loops only chunks with k0 <= p: excluded chunks contribute exactly
// (m=-1e30, l=0, acc=0), so the result is bit-identical.
__global__ void k_attn_reduce(float* __restrict__ out)
{
    int task = blockIdx.x * (blockDim.x >> 5) + (threadIdx.x >> 5);
    if (task >= BH * U) return;
    int lane = threadIdx.x & 31;
    int bh = task / U, u = task % U;
    int b = bh >> 3, h = bh & 7;

    int p = g_Mtop[bh * U + u];
    int ncc = (p >> 7) + 1;            // chunks 0..p/128 inclusive

    float m = -1e30f;
    for (int c = 0; c < ncc; c++) m = fmaxf(m, g_pm[task * NCHK + c]);
    float Lsum = 0.f;
    float2 a = make_float2(0.f, 0.f);
    for (int c = 0; c < ncc; c++) {
        float wgt = __expf(g_pm[task * NCHK + c] - m);
        Lsum += g_pl[task * NCHK + c] * wgt;
        float2 pa = *(const float2*)&g_pacc[(size_t)(task * NCHK + c) * D + 2 * lane];
        a.x += pa.x * wgt;
        a.y += pa.y * wgt;
    }
    float inv = 1.0f / Lsum;
    size_t o = (((size_t)b * L + p) * H + h) * D + 2 * lane;
    out[o + 0] = a.x * inv;
    out[o + 1] = a.y * inv;
}

// ===================== launch =====================
extern "C" void kernel_launch(void* const* d_in, const int* in_sizes, int n_in,
                              void* d_out, int out_size)
{
    const float* Q   = (const float*)d_in[0];
    const float* K   = (const float*)d_in[1];
    const float* V   = (const float*)d_in[2];
    const int*   idx = (const int*)d_in[3];
    float* out = (float*)d_out;

    // One-time host-side resources (no device memory involved).
    static cudaStream_t s2 = nullptr;
    static cudaEvent_t evFork = nullptr, evJoin = nullptr;
    if (!s2) {
        cudaStreamCreateWithFlags(&s2, cudaStreamNonBlocking);
        cudaEventCreateWithFlags(&evFork, cudaEventDisableTiming);
        cudaEventCreateWithFlags(&evJoin, cudaEventDisableTiming);
    }

    const int smem_a = (KCH * PKS + KCH * PVS + U * D + 8 * 5 * KCH) * (int)sizeof(float)
                     + U * (int)sizeof(int);
    cudaFuncSetAttribute(k_attn_partial, cudaFuncAttributeMaxDynamicSharedMemorySize, smem_a);

    // Fork: cumsum chain on side stream (round-13 topology: both under sample).
    cudaEventRecord(evFork, 0);
    cudaStreamWaitEvent(s2, evFork, 0);
    k_cumsum_a<<<B * NCH, C, 0, s2>>>(V);
    k_cumsum_c<<<B * NCH, C, 0, s2>>>(V, out);
    cudaEventRecord(evJoin, s2);

    // Main chain on default stream.
    k_sample_scores<<<L, 256>>>(Q, K, idx);
    k_topk<<<BH, 1024>>>();
    k_attn_partial<<<BH * NCHK, 256, smem_a>>>(Q, K, V);

    // Join: reduce overwrites the selected rows of out written by cumsum_c.
    cudaStreamWaitEvent(0, evJoin, 0);
    k_attn_reduce<<<(BH * U) / 8, 256>>>(out);
}

// round 17
// speedup vs baseline: 1.0817x; 1.0817x over previous
#include <cuda_runtime.h>
#include <cstdint>

// Shapes (fixed by the benchmark)
#define B 4
#define L 2048
#define H 8
#define D 64
#define SK 40          // sample_k
#define U 40           // top-k queries kept
#define BH (B*H)       // 32
#define C (H*D)        // 512 columns for cumsum view

// Attention chunking
#define KCH 128        // keys per chunk in dense attention
#define NCHK (L/KCH)   // 16
#define PKS 68         // Ks pitch (floats): 272B rows, 16B-aligned float4, conflict-free
#define PVS 68         // Vs pitch (floats): 272B rows, 16B-aligned float4 fills;
                       // float2 d-major reads conflict-free (68 mod 32 = 4 rotation)

// Cumsum chunking
#define NCH 128
#define CHUNK (L/NCH)  // 16

// -------- scratch (device globals; no allocation allowed) --------
__device__ float g_M[BH * L];
__device__ int   g_Mtop[BH * U];
__device__ float g_pm[BH * U * NCHK];
__device__ float g_pl[BH * U * NCHK];
__device__ float g_pacc[BH * U * NCHK * D];
__device__ float g_csum[B * NCH * C];

// ===================== Stage 1: sampled scores -> M =====================
// Block per query q. Thread t = (b=t>>6, h=(t>>3)&7, g=t&7); thread owns dims
// [8g, 8g+8). Samples in batches of 8: 16 independent LDG.128, 8 partial dots,
// 3-stage butterfly reduce-scatter (7 shuffles / 8 samples).
__global__ void __launch_bounds__(256) k_sample_scores(
    const float* __restrict__ Q,
    const float* __restrict__ K,
    const int*   __restrict__ idx)
{
    __shared__ int sidx[SK];
    int q = blockIdx.x;
    int t = threadIdx.x;
    int b = t >> 6;
    int h = (t >> 3) & 7;
    int g = t & 7;

    if (t < SK) sidx[t] = idx[q * SK + t];
    __syncthreads();

    const float* qp = Q + (((size_t)b * L + q) * H + h) * D + g * 8;
    float4 qa = *(const float4*)qp;
    float4 qb = *(const float4*)(qp + 4);

    const size_t hoff = (size_t)h * D + (size_t)g * 8;
    const float* Kb = K + (size_t)b * L * (H * D) + hoff;

    const int b0 = g & 1, b1 = (g >> 1) & 1, b2 = (g >> 2) & 1;

    float mx = -1e30f, sm = 0.f;

    for (int bi = 0; bi < 5; bi++) {
        float4 ka[8], kc[8];
        #pragma unroll
        for (int k = 0; k < 8; k++) {
            const float* kp = Kb + (size_t)sidx[bi * 8 + k] * (H * D);
            ka[k] = *(const float4*)kp;
            kc[k] = *(const float4*)(kp + 4);
        }
        float p[8];
        #pragma unroll
        for (int k = 0; k < 8; k++)
            p[k] = qa.x * ka[k].x + qa.y * ka[k].y + qa.z * ka[k].z + qa.w * ka[k].w
                 + qb.x * kc[k].x + qb.y * kc[k].y + qb.z * kc[k].z + qb.w * kc[k].w;

        float q4[4];
        #pragma unroll
        for (int j = 0; j < 4; j++) {
            float keep = b0 ? p[2 * j + 1] : p[2 * j];
            float send = b0 ? p[2 * j]     : p[2 * j + 1];
            q4[j] = keep + __shfl_xor_sync(0xffffffffu, send, 1);
        }
        float r2[2];
        #pragma unroll
        for (int j = 0; j < 2; j++) {
            float keep = b1 ? q4[2 * j + 1] : q4[2 * j];
            float send = b1 ? q4[2 * j]     : q4[2 * j + 1];
            r2[j] = keep + __shfl_xor_sync(0xffffffffu, send, 2);
        }
        float keep = b2 ? r2[1] : r2[0];
        float send = b2 ? r2[0] : r2[1];
        float d = keep + __shfl_xor_sync(0xffffffffu, send, 4);

        mx = fmaxf(mx, d);
        sm += d;
    }

    #pragma unroll
    for (int o = 1; o < 8; o <<= 1) {
        mx = fmaxf(mx, __shfl_xor_sync(0xffffffffu, mx, o));
        sm += __shfl_xor_sync(0xffffffffu, sm, o);
    }
    if (g == 0)
        g_M[(t >> 3) * L + q] = mx - sm * (1.0f / SK);
}

// ===================== Stage 2: exact top-U: 2 radix passes + rank =========
__device__ __forceinline__ unsigned f2ord(float f)
{
    unsigned u = __float_as_uint(f);
    return (u & 0x80000000u) ? ~u : (u | 0x80000000u);
}

#define CAND 1024

__global__ void __launch_bounds__(1024) k_topk()
{
    __shared__ unsigned keys[L];
    __shared__ int hist[256];
    __shared__ unsigned s_prefix;
    __shared__ int s_rem, s_cnt, s_ecnt;
    __shared__ int cand[CAND];
    __shared__ int tmpi[U];

    int bh = blockIdx.x;
    int t = threadIdx.x;

    unsigned k0 = f2ord(g_M[bh * L + t]);
    unsigned k1 = f2ord(g_M[bh * L + t + 1024]);
    keys[t] = k0;
    keys[t + 1024] = k1;
    if (t == 0) { s_prefix = 0u; s_rem = U; s_cnt = 0; s_ecnt = 0; }
    __syncthreads();

    unsigned mask = 0u;
    #pragma unroll
    for (int shift = 24; shift >= 16; shift -= 8) {
        if (t < 256) hist[t] = 0;
        __syncthreads();
        unsigned pre = s_prefix;
        if ((k0 & mask) == pre) atomicAdd(&hist[(k0 >> shift) & 255], 1);
        if ((k1 & mask) == pre) atomicAdd(&hist[(k1 >> shift) & 255], 1);
        __syncthreads();
        if (t < 32) {
            int rem = s_rem;
            int loc[8], sum = 0;
            #pragma unroll
            for (int j = 0; j < 8; j++) {
                loc[j] = hist[255 - (t * 8 + j)];
                sum += loc[j];
            }
            int pref = sum;
            #pragma unroll
            for (int o = 1; o < 32; o <<= 1) {
                int v = __shfl_up_sync(0xffffffffu, pref, o);
                if (t >= o) pref += v;
            }
            int c = pref - sum;
            #pragma unroll
            for (int j = 0; j < 8; j++) {
                int nc = c + loc[j];
                if (c < rem && nc >= rem) {        // exactly one (lane,j)
                    s_prefix = pre | ((unsigned)(255 - (t * 8 + j)) << shift);
                    s_rem = rem - c;
                }
                c = nc;
            }
        }
        mask |= (0xFFu << shift);
        __syncthreads();
    }

    unsigned pre16 = s_prefix;
    int rem = s_rem;
    {
        unsigned hi = k0 & 0xFFFF0000u;
        if (hi > pre16) tmpi[atomicAdd(&s_cnt, 1)] = t;
        else if (hi == pre16) {
            int p = atomicAdd(&s_ecnt, 1);
            if (p < CAND) cand[p] = t;
        }
        hi = k1 & 0xFFFF0000u;
        if (hi > pre16) tmpi[atomicAdd(&s_cnt, 1)] = t + 1024;
        else if (hi == pre16) {
            int p = atomicAdd(&s_ecnt, 1);
            if (p < CAND) cand[p] = t + 1024;
        }
    }
    __syncthreads();

    int ncand = min(s_ecnt, CAND);
    int base = s_cnt;                        // == U - rem by construction
    if (t < ncand) {
        int i = cand[t];
        unsigned k = keys[i];
        int rank = 0;
        for (int j = 0; j < ncand; j++) {
            int cj = cand[j];
            unsigned kj = keys[cj];
            rank += (kj > k) || (kj == k && cj < i);
        }
        if (rank < rem) tmpi[base + rank] = i;
    }
    __syncthreads();

    // rank-sort ascending (indices distinct); g_Mtop consumed as a set
    if (t < U) {
        int v = tmpi[t], r = 0;
        #pragma unroll
        for (int j = 0; j < U; j++) r += (tmpi[j] < v);
        g_Mtop[bh * U + r] = v;
    }
}

// ===================== Stage 3: cumsum of V along L -> out =====================
__global__ void k_cumsum_a(const float* __restrict__ V)
{
    int blk = blockIdx.x;
    int b = blk / NCH, ch = blk % NCH;
    int c = threadIdx.x;
    const float* base = V + ((size_t)b * L + ch * CHUNK) * C + c;
    float s = 0.f;
    #pragma unroll
    for (int l = 0; l < CHUNK; l++) s += base[(size_t)l * C];
    g_csum[((size_t)b * NCH + ch) * C + c] = s;
}

__global__ void k_cumsum_c(const float* __restrict__ V, float* __restrict__ out)
{
    int blk = blockIdx.x;
    int b = blk / NCH, ch = blk % NCH;
    int c = threadIdx.x;
    float run = 0.f;
    for (int j = 0; j < ch; j++)
        run += g_csum[((size_t)b * NCH + j) * C + c];
    const float* vb = V   + ((size_t)b * L + ch * CHUNK) * C + c;
    float*       ob = out + ((size_t)b * L + ch * CHUNK) * C + c;
    #pragma unroll
    for (int l0 = 0; l0 < CHUNK; l0 += 8) {
        float v[8];
        #pragma unroll
        for (int j = 0; j < 8; j++) v[j] = vb[(size_t)(l0 + j) * C];
        #pragma unroll
        for (int j = 0; j < 8; j++) {
            run += v[j];
            ob[(size_t)(l0 + j) * C] = run;
        }
    }
}

// ===================== Stage 4: dense attention partials =====================
// K/V/Q smem fills vectorized to float4 (4x fewer LDG/STS in the serial
// prologue; PVS=68 keeps every row 16B-aligned). Skipped (warp,chunk) pairs
// write NOTHING; the reduce kernel loops only chunks with k0 <= p.
__global__ void __launch_bounds__(256) k_attn_partial(
    const float* __restrict__ Q,
    const float* __restrict__ K,
    const float* __restrict__ V)
{
    extern __shared__ float smf[];
    float* Ks = smf;                       // KCH * PKS
    float* Vs = Ks + KCH * PKS;            // KCH * PVS
    float* Qs = Vs + KCH * PVS;            // U * D
    float* pb = Qs + U * D;                // 8 warps * 5 q * 128 k
    int*   ps = (int*)(pb + 8 * 5 * KCH);  // U

    int bh = blockIdx.x >> 4;
    int ch = blockIdx.x & 15;
    int b = bh >> 3, h = bh & 7;
    int t = threadIdx.x;
    int k0 = ch * KCH;

    // K/V chunk: 2048 float4s, 8 iters of 256 threads (16 float4/row)
    #pragma unroll
    for (int j = 0; j < 8; j++) {
        int i = t + j * 256;
        int r = i >> 4, d4 = (i & 15) << 2;
        size_t gidx = (((size_t)b * L + (k0 + r)) * H + h) * D + d4;
        *(float4*)&Ks[r * PKS + d4] = *(const float4*)&K[gidx];
        *(float4*)&Vs[r * PVS + d4] = *(const float4*)&V[gidx];
    }
    if (t < U) ps[t] = g_Mtop[bh * U + t];
    __syncthreads();
    // Q rows: 640 float4s
    for (int i = t; i < U * (D / 4); i += 256) {
        int u = i >> 4, d4 = (i & 15) << 2;
        *(float4*)&Qs[u * D + d4] =
            *(const float4*)&Q[(((size_t)b * L + ps[u]) * H + h) * D + d4];
    }
    __syncthreads();

    int w = t >> 5, lane = t & 31;
    const float4* Qb = (const float4*)Qs;

    // whole-warp causal skip (ps sorted ascending; no block barriers below).
    // Reduce never reads these (chunk,query) slots -> no writes needed.
    if (ps[w * 5 + 4] < k0) return;

    float s4[5][4];
    #pragma unroll
    for (int q = 0; q < 5; q++)
        #pragma unroll
        for (int g = 0; g < 4; g++) s4[q][g] = 0.f;

    #pragma unroll 4
    for (int i = 0; i < 16; i++) {
        float4 kk[4];
        #pragma unroll
        for (int g = 0; g < 4; g++)
            kk[g] = *(const float4*)&Ks[(g * 32 + lane) * PKS + 4 * i];
        #pragma unroll
        for (int q = 0; q < 5; q++) {
            float4 qv = Qb[(w * 5 + q) * 16 + i];
            #pragma unroll
            for (int g = 0; g < 4; g++)
                s4[q][g] += qv.x * kk[g].x + qv.y * kk[g].y
                          + qv.z * kk[g].z + qv.w * kk[g].w;
        }
    }

    #pragma unroll
    for (int q = 0; q < 5; q++) {
        int u = w * 5 + q;
        int p = ps[u];
        float sc[4]; bool ok[4];
        float m = -1e30f;
        #pragma unroll
        for (int g = 0; g < 4; g++) {
            sc[g] = s4[q][g] * 0.125f;             // 1/sqrt(64)
            ok[g] = (k0 + g * 32 + lane) <= p;
            m = fmaxf(m, ok[g] ? sc[g] : -1e30f);
        }
        #pragma unroll
        for (int o = 16; o; o >>= 1)
            m = fmaxf(m, __shfl_xor_sync(0xffffffffu, m, o));
        float l = 0.f;
        #pragma unroll
        for (int g = 0; g < 4; g++) {
            float pv = ok[g] ? __expf(sc[g] - m) : 0.f;
            l += pv;
            pb[w * (5 * KCH) + q * KCH + g * 32 + lane] = pv;
        }
        #pragma unroll
        for (int o = 16; o; o >>= 1)
            l += __shfl_xor_sync(0xffffffffu, l, o);
        if (lane == 0) {
            int pi = (bh * U + u) * NCHK + ch;
            g_pm[pi] = m;
            g_pl[pi] = l;
        }
    }
    __syncwarp();

    float2 acc[5];
    #pragma unroll
    for (int q = 0; q < 5; q++) acc[q] = make_float2(0.f, 0.f);

    #pragma unroll 4
    for (int k = 0; k < KCH; k += 4) {
        float2 v0 = *(const float2*)&Vs[(k + 0) * PVS + 2 * lane];
        float2 v1 = *(const float2*)&Vs[(k + 1) * PVS + 2 * lane];
        float2 v2 = *(const float2*)&Vs[(k + 2) * PVS + 2 * lane];
        float2 v3 = *(const float2*)&Vs[(k + 3) * PVS + 2 * lane];
        #pragma unroll
        for (int q = 0; q < 5; q++) {
            float4 pq = *(const float4*)&pb[w * (5 * KCH) + q * KCH + k];
            acc[q].x += pq.x * v0.x + pq.y * v1.x + pq.z * v2.x + pq.w * v3.x;
            acc[q].y += pq.x * v0.y + pq.y * v1.y + pq.z * v2.y + pq.w * v3.y;
        }
    }

    #pragma unroll
    for (int q = 0; q < 5; q++) {
        int u = w * 5 + q;
        int pi = (bh * U + u) * NCHK + ch;
        *(float2*)&g_pacc[(size_t)pi * D + 2 * lane] = acc[q];
    }
}

// ===================== Stage 5: combine partials, scatter rows =====================
// Loops only chunks with k0 <= p: excluded chunks contribute exactly
// (m=-1e30, l=0, acc=0), so the result is bit-identical.
__global__ void k_attn_reduce(float* __restrict__ out)
{
    int task = blockIdx.x * (blockDim.x >> 5) + (threadIdx.x >> 5);
    if (task >= BH * U) return;
    int lane = threadIdx.x & 31;
    int bh = task / U, u = task % U;
    int b = bh >> 3, h = bh & 7;

    int p = g_Mtop[bh * U + u];
    int ncc = (p >> 7) + 1;            // chunks 0..p/128 inclusive

    float m = -1e30f;
    for (int c = 0; c < ncc; c++) m = fmaxf(m, g_pm[task * NCHK + c]);
    float Lsum = 0.f;
    float2 a = make_float2(0.f, 0.f);
    for (int c = 0; c < ncc; c++) {
        float wgt = __expf(g_pm[task * NCHK + c] - m);
        Lsum += g_pl[task * NCHK + c] * wgt;
        float2 pa = *(const float2*)&g_pacc[(size_t)(task * NCHK + c) * D + 2 * lane];
        a.x += pa.x * wgt;
        a.y += pa.y * wgt;
    }
    float inv = 1.0f / Lsum;
    size_t o = (((size_t)b * L + p) * H + h) * D + 2 * lane;
    out[o + 0] = a.x * inv;
    out[o + 1] = a.y * inv;
}

// ===================== launch =====================
extern "C" void kernel_launch(void* const* d_in, const int* in_sizes, int n_in,
                              void* d_out, int out_size)
{
    const float* Q   = (const float*)d_in[0];
    const float* K   = (const float*)d_in[1];
    const float* V   = (const float*)d_in[2];
    const int*   idx = (const int*)d_in[3];
    float* out = (float*)d_out;

    // One-time host-side resources (no device memory involved).
    static cudaStream_t s2 = nullptr;
    static cudaEvent_t evFork = nullptr, evJoin = nullptr;
    if (!s2) {
        cudaStreamCreateWithFlags(&s2, cudaStreamNonBlocking);
        cudaEventCreateWithFlags(&evFork, cudaEventDisableTiming);
        cudaEventCreateWithFlags(&evJoin, cudaEventDisableTiming);
    }

    const int smem_a = (KCH * PKS + KCH * PVS + U * D + 8 * 5 * KCH) * (int)sizeof(float)
                     + U * (int)sizeof(int);
    cudaFuncSetAttribute(k_attn_partial, cudaFuncAttributeMaxDynamicSharedMemorySize, smem_a);

    // Fork: cumsum chain on side stream (round-13 topology: both under sample).
    cudaEventRecord(evFork, 0);
    cudaStreamWaitEvent(s2, evFork, 0);
    k_cumsum_a<<<B * NCH, C, 0, s2>>>(V);
    k_cumsum_c<<<B * NCH, C, 0, s2>>>(V, out);
    cudaEventRecord(evJoin, s2);

    // Main chain on default stream.
    k_sample_scores<<<L, 256>>>(Q, K, idx);
    k_topk<<<BH, 1024>>>();
    k_attn_partial<<<BH * NCHK, 256, smem_a>>>(Q, K, V);

    // Join: reduce overwrites the selected rows of out written by cumsum_c.
    cudaStreamWaitEvent(0, evJoin, 0);
    k_attn_reduce<<<(BH * U) / 8, 256>>>(out);
}